// round 9
// baseline (speedup 1.0000x reference)
#include <cuda_runtime.h>

#define BN 8
#define NP 2000
#define NG 100
#define MH 320
#define MW 320
#define NUM_POS 66
#define NUM_NEG 134
#define TRAIN_ROIS 200
#define MASK_H 28
#define MASK_W 28

// output layout (flattened tuple, float32)
#define ROIS_OFF  0
#define CLS_OFF   (BN*TRAIN_ROIS*4)            /* 6400 */
#define DELTA_OFF (CLS_OFF + BN*TRAIN_ROIS)    /* 8000 */
#define MASK_OFF  (DELTA_OFF + BN*TRAIN_ROIS*4)/* 14400 */

__device__ unsigned g_keyhi[BN*NP];   // ~orderable(maxiou): ascending = value desc
__device__ int      g_arg[BN*NP];
__device__ unsigned char g_valid[BN*NP];
__device__ int g_poslist[BN*NUM_POS];
__device__ int g_poscount[BN];

// XLA GPU compiles f32 divide with nvptx-prec-divf32=1 -> div.full.f32.
__device__ __forceinline__ float xdiv(float a, float b) {
    float r;
    asm("div.full.f32 %0, %1, %2;" : "=f"(r) : "f"(a), "f"(b));
    return r;
}

__device__ __forceinline__ unsigned orderable(float v) {
    unsigned u = __float_as_uint(v);
    return (u & 0x80000000u) ? ~u : (u | 0x80000000u);
}
// v >= 0.5 <=> hi = ~ord(v) <= ~ord(0.5) = 0x40FFFFFF
__device__ __forceinline__ int pos_hi(unsigned hi) { return hi <= 0x40FFFFFFu; }

// ---------------------------------------------------------------------------
// Kernel 1: IoU max/argmax. One batch per grid.y; GTs staged in shared once
// per block. 8 threads per proposal (13/12 GTs each) + shuffle max-reduce of
// packed (orderable(v)<<32)|(NG-1-g): max = highest value, tie -> lowest g,
// identical to sequential first-max (jnp.argmax).
// ---------------------------------------------------------------------------
__global__ __launch_bounds__(512) void iou_kernel(const float4* __restrict__ props,
                                                  const float4* __restrict__ gts)
{
    __shared__ float4 sg[NG];
    __shared__ unsigned char svg[NG];

    int b = blockIdx.y;
    int tid = threadIdx.x;

    if (tid < NG) {
        float4 q = gts[b*NG + tid];
        sg[tid] = q;
        svg[tid] = (q.x!=0.f)||(q.y!=0.f)||(q.z!=0.f)||(q.w!=0.f);
    }
    __syncthreads();

    int task = blockIdx.x * 512 + tid;     // 8 tasks per proposal
    int pi   = task >> 3;                  // proposal within batch
    int sub  = task & 7;
    if (pi >= NP) return;
    int pid = b*NP + pi;

    float4 p = props[pid];
    unsigned char valid = (p.x!=0.f)||(p.y!=0.f)||(p.z!=0.f)||(p.w!=0.f);
    float area_a = __fmul_rn(__fsub_rn(p.z,p.x), __fsub_rn(p.w,p.y));

    // sub<4 handle 13 GTs, sub>=4 handle 12 (4*13+4*12 = 100)
    int g0  = (sub < 4) ? sub*13 : 52 + (sub-4)*12;
    int cnt = (sub < 4) ? 13 : 12;

    unsigned long long bestk = 0ull;       // candidate keys always > 0
    #pragma unroll 13
    for (int gg = 0; gg < 13; ++gg) {
        if (gg >= cnt) break;
        int g = g0 + gg;
        float4 q = sg[g];
        float y1 = fmaxf(p.x, q.x), x1 = fmaxf(p.y, q.y);
        float y2 = fminf(p.z, q.z), x2 = fminf(p.w, q.w);
        float inter = __fmul_rn(fmaxf(__fsub_rn(y2,y1),0.f),
                                fmaxf(__fsub_rn(x2,x1),0.f));
        float area_b = __fmul_rn(__fsub_rn(q.z,q.x), __fsub_rn(q.w,q.y));
        float uni = __fsub_rn(__fadd_rn(area_a, area_b), inter);
        float iou = xdiv(inter, fmaxf(uni, 1e-8f));
        float v = (svg[g] && valid) ? iou : -1.0f;
        unsigned long long k = (((unsigned long long)orderable(v)) << 32)
                             | (unsigned)(NG - 1 - g);
        if (k > bestk) bestk = k;
    }

    // reduce across the 8 lanes of this proposal (8-aligned within warp)
    #pragma unroll
    for (int off = 1; off < 8; off <<= 1) {
        unsigned long long o = __shfl_xor_sync(0xFFFFFFFFu, bestk, off);
        if (o > bestk) bestk = o;
    }

    if (sub == 0) {
        g_keyhi[pid] = ~((unsigned)(bestk >> 32));
        g_arg[pid]   = NG - 1 - (int)(bestk & 0xFFFFFFFFu);
        g_valid[pid] = valid;
    }
}

// ---------------------------------------------------------------------------
// Kernel 2 (one block of 1024 per batch): sort + select + slots.
// Bitonic sort of 2048 keys (value desc, idx asc); strides j<=32 are
// warp-local, so only phases touching j>=64 need __syncthreads. Filtered
// extraction via warp-shuffle scans. Tail computes rois/class/deltas.
// ---------------------------------------------------------------------------
__global__ __launch_bounds__(1024) void select_kernel(const float4* __restrict__ props,
                                                      const float4* __restrict__ gts,
                                                      const int*    __restrict__ cls,
                                                      float* __restrict__ out)
{
    int b = blockIdx.x, t = threadIdx.x;
    int lane = t & 31, wid = t >> 5;
    __shared__ unsigned long long keys[2048];
    __shared__ unsigned char svalid[2048];
    __shared__ int warpsum[32];
    __shared__ int s_pos[NUM_POS];
    __shared__ int s_neg[NUM_NEG];
    __shared__ int s_cnt[4];   // totpos, totneg, pc, nc

    // load packed keys: (keyhi << 32) | idx ; padding sorts to end
    #pragma unroll
    for (int rep = 0; rep < 2; ++rep) {
        int i = t + rep*1024;
        unsigned long long k = ~0ull;
        unsigned char v = 0;
        if (i < NP) {
            k = (((unsigned long long)g_keyhi[b*NP + i]) << 32) | (unsigned)i;
            v = g_valid[b*NP + i];
        }
        keys[i] = k;
        svalid[i] = v;
    }

    // ---- bitonic sort ascending ----
    int prevj = 1 << 30;
    for (int kk = 2; kk <= 2048; kk <<= 1) {
        for (int j = kk >> 1; j > 0; j >>= 1) {
            if (j >= 64 || prevj >= 64) __syncthreads(); else __syncwarp();
            int i  = ((t & ~(j-1)) << 1) | (t & (j-1));
            int ix = i | j;
            bool up = ((i & kk) == 0);
            unsigned long long a = keys[i], c = keys[ix];
            if ((a > c) == up) { keys[i] = c; keys[ix] = a; }
            prevj = j;
        }
    }
    __syncthreads();

    // ---- filtered extraction (pass 0: pos, pass 1: neg) ----
    for (int pass = 0; pass < 2; ++pass) {
        unsigned long long k0 = keys[2*t], k1 = keys[2*t+1];
        unsigned hi0 = (unsigned)(k0 >> 32), hi1 = (unsigned)(k1 >> 32);
        unsigned id0 = (unsigned)(k0 & 0xFFFFFFFFu), id1 = (unsigned)(k1 & 0xFFFFFFFFu);
        int fa, fb;
        if (pass == 0) {
            fa = pos_hi(hi0);
            fb = pos_hi(hi1);
        } else {
            fa = (id0 < NP) && !pos_hi(hi0) && svalid[id0];
            fb = (id1 < NP) && !pos_hi(hi1) && svalid[id1];
        }
        int s = fa + fb;
        int x = s;
        #pragma unroll
        for (int off = 1; off < 32; off <<= 1) {
            int y = __shfl_up_sync(0xFFFFFFFFu, x, off);
            if (lane >= off) x += y;
        }
        if (lane == 31) warpsum[wid] = x;
        __syncthreads();
        if (t < 32) {
            int v = warpsum[t];
            #pragma unroll
            for (int off = 1; off < 32; off <<= 1) {
                int y = __shfl_up_sync(0xFFFFFFFFu, v, off);
                if (t >= off) v += y;
            }
            warpsum[t] = v;
        }
        __syncthreads();
        int incl = x + (wid ? warpsum[wid-1] : 0);
        int excl = incl - s;
        if (pass == 0) {
            if (fa && excl < NUM_POS)        s_pos[excl]      = (int)id0;
            if (fb && (excl + fa) < NUM_POS) s_pos[excl + fa] = (int)id1;
        } else {
            if (fa && excl < NUM_NEG)        s_neg[excl]      = (int)id0;
            if (fb && (excl + fa) < NUM_NEG) s_neg[excl + fa] = (int)id1;
        }
        if (t == 0) s_cnt[pass] = warpsum[31];
        __syncthreads();
    }

    if (t == 0) {
        int pc = min(s_cnt[0], NUM_POS);
        int nc = (int)xdiv((float)pc, 0.33f) - pc;   // reference's div.full
        nc = min(nc, s_cnt[1]);
        nc = min(nc, NUM_NEG);
        if (nc < 0) nc = 0;
        s_cnt[2] = pc;
        s_cnt[3] = nc;
        g_poscount[b] = pc;
    }
    __syncthreads();
    int pc = s_cnt[2], nc = s_cnt[3];

    // publish poslist for the mask kernel
    if (t < NUM_POS && t < pc) g_poslist[b*NUM_POS + t] = s_pos[t];

    // ---- slots tail: rois / class / deltas for all 200 slots ----
    if (t < TRAIN_ROIS) {
        float4 roi = make_float4(0.f,0.f,0.f,0.f);
        float  c   = 0.f;
        float4 dd  = make_float4(0.f,0.f,0.f,0.f);

        if (t < NUM_POS) {
            if (t < pc) {
                int p = s_pos[t];
                float4 r = props[b*NP + p];
                roi = r;
                int g = g_arg[b*NP + p];
                c = (float)cls[b*NG + g];
                float4 q = gts[b*NG + g];
                float h  = fmaxf(__fsub_rn(r.z,r.x), 1e-8f);
                float w  = fmaxf(__fsub_rn(r.w,r.y), 1e-8f);
                float cy = __fadd_rn(r.x, __fmul_rn(0.5f,h));
                float cx = __fadd_rn(r.y, __fmul_rn(0.5f,w));
                float gh  = fmaxf(__fsub_rn(q.z,q.x), 1e-8f);
                float gw  = fmaxf(__fsub_rn(q.w,q.y), 1e-8f);
                float gcy = __fadd_rn(q.x, __fmul_rn(0.5f,gh));
                float gcx = __fadd_rn(q.y, __fmul_rn(0.5f,gw));
                dd.x = xdiv(xdiv(__fsub_rn(gcy,cy), h), 0.1f);
                dd.y = xdiv(xdiv(__fsub_rn(gcx,cx), w), 0.1f);
                dd.z = xdiv(logf(xdiv(gh,h)), 0.2f);
                dd.w = xdiv(logf(xdiv(gw,w)), 0.2f);
            }
        } else {
            int j = t - NUM_POS;
            if (j < nc) {
                int p = s_neg[j];
                roi = props[b*NP + p];
            }
        }

        ((float4*)(out + ROIS_OFF))[b*TRAIN_ROIS + t]  = roi;
        out[CLS_OFF + b*TRAIN_ROIS + t]                = c;
        ((float4*)(out + DELTA_OFF))[b*TRAIN_ROIS + t] = dd;
    }
}

// ---------------------------------------------------------------------------
// Kernel 3: masks for ALL 200 slots per batch (bilinear crop for selected
// positives, zeros elsewhere).
// ---------------------------------------------------------------------------
__global__ void mask_kernel(const float4* __restrict__ props,
                            const unsigned int* __restrict__ masks,
                            float* __restrict__ out)
{
    int b = blockIdx.y, i = blockIdx.x;
    int t = threadIdx.x;                  // 0..783
    float* dst = out + MASK_OFF + ((size_t)b*TRAIN_ROIS + i)*(MASK_H*MASK_W);

    if (i >= g_poscount[b]) { dst[t] = 0.0f; return; }

    int p = g_poslist[b*NUM_POS + i];
    float4 r = props[b*NP + p];
    int g = g_arg[b*NP + p];

    int y = t / MASK_W, x = t % MASK_W;

    float fy = xdiv((float)y, (float)(MASK_H-1));
    float fx = xdiv((float)x, (float)(MASK_W-1));
    float sy = __fadd_rn(__fmul_rn(r.x, 319.f),
                         __fmul_rn(__fmul_rn(fy, __fsub_rn(r.z,r.x)), 319.f));
    sy = fminf(fmaxf(sy, 0.f), 319.f);
    float sx = __fadd_rn(__fmul_rn(r.y, 319.f),
                         __fmul_rn(__fmul_rn(fx, __fsub_rn(r.w,r.y)), 319.f));
    sx = fminf(fmaxf(sx, 0.f), 319.f);

    int y0 = min(max((int)floorf(sy), 0), MH-2);
    int x0 = min(max((int)floorf(sx), 0), MW-2);
    float wy = __fsub_rn(sy, (float)y0);
    float wx = __fsub_rn(sx, (float)x0);

    size_t i00 = (((size_t)b*MH + y0)*MW + x0)*NG + g;
    float c00 = masks[i00]                    ? 1.f : 0.f;
    float c01 = masks[i00 + NG]               ? 1.f : 0.f;
    float c10 = masks[i00 + (size_t)MW*NG]    ? 1.f : 0.f;
    float c11 = masks[i00 + (size_t)MW*NG+NG] ? 1.f : 0.f;

    float top = __fadd_rn(__fmul_rn(c00, __fsub_rn(1.f,wx)), __fmul_rn(c01, wx));
    float bot = __fadd_rn(__fmul_rn(c10, __fsub_rn(1.f,wx)), __fmul_rn(c11, wx));
    float val = __fadd_rn(__fmul_rn(top, __fsub_rn(1.f,wy)), __fmul_rn(bot, wy));

    dst[t] = rintf(val);
}

// ---------------------------------------------------------------------------
extern "C" void kernel_launch(void* const* d_in, const int* in_sizes, int n_in,
                              void* d_out, int out_size)
{
    const float4*       props = 0;
    const int*          cls   = 0;
    const float4*       gts   = 0;
    const unsigned int* masks = 0;
    for (int i = 0; i < n_in; ++i) {
        switch (in_sizes[i]) {
            case BN*NP*4:              props = (const float4*)d_in[i];       break;
            case BN*NG:                cls   = (const int*)d_in[i];          break;
            case BN*NG*4:              gts   = (const float4*)d_in[i];       break;
            default:                   masks = (const unsigned int*)d_in[i]; break;
        }
    }
    float* out = (float*)d_out;

    iou_kernel<<<dim3((NP*8 + 511)/512, BN), 512>>>(props, gts);
    select_kernel<<<BN, 1024>>>(props, gts, cls, out);
    mask_kernel<<<dim3(TRAIN_ROIS, BN), MASK_H*MASK_W>>>(props, masks, out);
}

// round 10
// speedup vs baseline: 1.0413x; 1.0413x over previous
#include <cuda_runtime.h>

#define BN 8
#define NP 2000
#define NG 100
#define MH 320
#define MW 320
#define NUM_POS 66
#define NUM_NEG 134
#define TRAIN_ROIS 200
#define MASK_H 28
#define MASK_W 28

// output layout (flattened tuple, float32)
#define ROIS_OFF  0
#define CLS_OFF   (BN*TRAIN_ROIS*4)            /* 6400 */
#define DELTA_OFF (CLS_OFF + BN*TRAIN_ROIS)    /* 8000 */
#define MASK_OFF  (DELTA_OFF + BN*TRAIN_ROIS*4)/* 14400 */

__device__ unsigned g_keyhi[BN*NP];   // ~orderable(maxiou): ascending = value desc
__device__ int      g_arg[BN*NP];
__device__ unsigned char g_valid[BN*NP];
__device__ int g_poslist[BN*NUM_POS];
__device__ int g_poscount[BN];

// XLA GPU compiles f32 divide with nvptx-prec-divf32=1 -> div.full.f32.
__device__ __forceinline__ float xdiv(float a, float b) {
    float r;
    asm("div.full.f32 %0, %1, %2;" : "=f"(r) : "f"(a), "f"(b));
    return r;
}

__device__ __forceinline__ unsigned orderable(float v) {
    unsigned u = __float_as_uint(v);
    return (u & 0x80000000u) ? ~u : (u | 0x80000000u);
}
// v >= 0.5 <=> hi = ~ord(v) <= ~ord(0.5) = 0x40FFFFFF
__device__ __forceinline__ int pos_hi(unsigned hi) { return hi <= 0x40FFFFFFu; }

// ---------------------------------------------------------------------------
// Kernel 1: IoU max/argmax. One batch per grid.y; GTs staged in shared once
// per 256-thread block. 4 threads per proposal (25 GTs each, R8 shape) +
// shuffle max-reduce of packed (orderable(v)<<32)|(NG-1-g): max = highest
// value, tie -> lowest g = sequential first-max (jnp.argmax).
// ---------------------------------------------------------------------------
__global__ __launch_bounds__(256) void iou_kernel(const float4* __restrict__ props,
                                                  const float4* __restrict__ gts)
{
    __shared__ float4 sg[NG];
    __shared__ unsigned char svg[NG];

    int b = blockIdx.y;
    int tid = threadIdx.x;

    if (tid < NG) {
        float4 q = gts[b*NG + tid];
        sg[tid] = q;
        svg[tid] = (q.x!=0.f)||(q.y!=0.f)||(q.z!=0.f)||(q.w!=0.f);
    }
    __syncthreads();

    int task = blockIdx.x * 256 + tid;   // 4 tasks per proposal
    int pi   = task >> 2;                // proposal within batch
    int sub  = task & 3;
    if (pi >= NP) return;
    int pid = b*NP + pi;

    float4 p = props[pid];
    unsigned char valid = (p.x!=0.f)||(p.y!=0.f)||(p.z!=0.f)||(p.w!=0.f);
    float area_a = __fmul_rn(__fsub_rn(p.z,p.x), __fsub_rn(p.w,p.y));

    unsigned long long bestk = 0ull;     // candidate keys always > 0
    int g0 = sub * (NG/4);
    #pragma unroll 5
    for (int gg = 0; gg < NG/4; ++gg) {
        int g = g0 + gg;
        float4 q = sg[g];
        float y1 = fmaxf(p.x, q.x), x1 = fmaxf(p.y, q.y);
        float y2 = fminf(p.z, q.z), x2 = fminf(p.w, q.w);
        float inter = __fmul_rn(fmaxf(__fsub_rn(y2,y1),0.f),
                                fmaxf(__fsub_rn(x2,x1),0.f));
        float area_b = __fmul_rn(__fsub_rn(q.z,q.x), __fsub_rn(q.w,q.y));
        float uni = __fsub_rn(__fadd_rn(area_a, area_b), inter);
        float iou = xdiv(inter, fmaxf(uni, 1e-8f));
        float v = (svg[g] && valid) ? iou : -1.0f;
        unsigned long long k = (((unsigned long long)orderable(v)) << 32)
                             | (unsigned)(NG - 1 - g);
        if (k > bestk) bestk = k;
    }

    // reduce across the 4 threads of this proposal (4-aligned within warp)
    #pragma unroll
    for (int off = 1; off < 4; off <<= 1) {
        unsigned long long o = __shfl_xor_sync(0xFFFFFFFFu, bestk, off);
        if (o > bestk) bestk = o;
    }

    if (sub == 0) {
        g_keyhi[pid] = ~((unsigned)(bestk >> 32));
        g_arg[pid]   = NG - 1 - (int)(bestk & 0xFFFFFFFFu);
        g_valid[pid] = valid;
    }
}

// ---------------------------------------------------------------------------
// Kernel 2 (one block of 1024 per batch): sort + select + slots.
// Bitonic sort of 2048 keys (value desc, idx asc); strides j<=32 are
// warp-local, so only phases touching j>=64 need __syncthreads. Filtered
// extraction via warp-shuffle scans. Tail computes rois/class/deltas.
// ---------------------------------------------------------------------------
__global__ __launch_bounds__(1024) void select_kernel(const float4* __restrict__ props,
                                                      const float4* __restrict__ gts,
                                                      const int*    __restrict__ cls,
                                                      float* __restrict__ out)
{
    int b = blockIdx.x, t = threadIdx.x;
    int lane = t & 31, wid = t >> 5;
    __shared__ unsigned long long keys[2048];
    __shared__ unsigned char svalid[2048];
    __shared__ int warpsum[32];
    __shared__ int s_pos[NUM_POS];
    __shared__ int s_neg[NUM_NEG];
    __shared__ int s_cnt[4];   // totpos, totneg, pc, nc

    // load packed keys: (keyhi << 32) | idx ; padding sorts to end
    #pragma unroll
    for (int rep = 0; rep < 2; ++rep) {
        int i = t + rep*1024;
        unsigned long long k = ~0ull;
        unsigned char v = 0;
        if (i < NP) {
            k = (((unsigned long long)g_keyhi[b*NP + i]) << 32) | (unsigned)i;
            v = g_valid[b*NP + i];
        }
        keys[i] = k;
        svalid[i] = v;
    }

    // ---- bitonic sort ascending ----
    int prevj = 1 << 30;
    for (int kk = 2; kk <= 2048; kk <<= 1) {
        for (int j = kk >> 1; j > 0; j >>= 1) {
            if (j >= 64 || prevj >= 64) __syncthreads(); else __syncwarp();
            int i  = ((t & ~(j-1)) << 1) | (t & (j-1));
            int ix = i | j;
            bool up = ((i & kk) == 0);
            unsigned long long a = keys[i], c = keys[ix];
            if ((a > c) == up) { keys[i] = c; keys[ix] = a; }
            prevj = j;
        }
    }
    __syncthreads();

    // ---- filtered extraction (pass 0: pos, pass 1: neg) ----
    for (int pass = 0; pass < 2; ++pass) {
        unsigned long long k0 = keys[2*t], k1 = keys[2*t+1];
        unsigned hi0 = (unsigned)(k0 >> 32), hi1 = (unsigned)(k1 >> 32);
        unsigned id0 = (unsigned)(k0 & 0xFFFFFFFFu), id1 = (unsigned)(k1 & 0xFFFFFFFFu);
        int fa, fb;
        if (pass == 0) {
            fa = pos_hi(hi0);
            fb = pos_hi(hi1);
        } else {
            fa = (id0 < NP) && !pos_hi(hi0) && svalid[id0];
            fb = (id1 < NP) && !pos_hi(hi1) && svalid[id1];
        }
        int s = fa + fb;
        int x = s;
        #pragma unroll
        for (int off = 1; off < 32; off <<= 1) {
            int y = __shfl_up_sync(0xFFFFFFFFu, x, off);
            if (lane >= off) x += y;
        }
        if (lane == 31) warpsum[wid] = x;
        __syncthreads();
        if (t < 32) {
            int v = warpsum[t];
            #pragma unroll
            for (int off = 1; off < 32; off <<= 1) {
                int y = __shfl_up_sync(0xFFFFFFFFu, v, off);
                if (t >= off) v += y;
            }
            warpsum[t] = v;
        }
        __syncthreads();
        int incl = x + (wid ? warpsum[wid-1] : 0);
        int excl = incl - s;
        if (pass == 0) {
            if (fa && excl < NUM_POS)        s_pos[excl]      = (int)id0;
            if (fb && (excl + fa) < NUM_POS) s_pos[excl + fa] = (int)id1;
        } else {
            if (fa && excl < NUM_NEG)        s_neg[excl]      = (int)id0;
            if (fb && (excl + fa) < NUM_NEG) s_neg[excl + fa] = (int)id1;
        }
        if (t == 0) s_cnt[pass] = warpsum[31];
        __syncthreads();
    }

    if (t == 0) {
        int pc = min(s_cnt[0], NUM_POS);
        int nc = (int)xdiv((float)pc, 0.33f) - pc;   // reference's div.full
        nc = min(nc, s_cnt[1]);
        nc = min(nc, NUM_NEG);
        if (nc < 0) nc = 0;
        s_cnt[2] = pc;
        s_cnt[3] = nc;
        g_poscount[b] = pc;
    }
    __syncthreads();
    int pc = s_cnt[2], nc = s_cnt[3];

    // publish poslist for the mask kernel
    if (t < NUM_POS && t < pc) g_poslist[b*NUM_POS + t] = s_pos[t];

    // ---- slots tail: rois / class / deltas for all 200 slots ----
    if (t < TRAIN_ROIS) {
        float4 roi = make_float4(0.f,0.f,0.f,0.f);
        float  c   = 0.f;
        float4 dd  = make_float4(0.f,0.f,0.f,0.f);

        if (t < NUM_POS) {
            if (t < pc) {
                int p = s_pos[t];
                float4 r = props[b*NP + p];
                roi = r;
                int g = g_arg[b*NP + p];
                c = (float)cls[b*NG + g];
                float4 q = gts[b*NG + g];
                float h  = fmaxf(__fsub_rn(r.z,r.x), 1e-8f);
                float w  = fmaxf(__fsub_rn(r.w,r.y), 1e-8f);
                float cy = __fadd_rn(r.x, __fmul_rn(0.5f,h));
                float cx = __fadd_rn(r.y, __fmul_rn(0.5f,w));
                float gh  = fmaxf(__fsub_rn(q.z,q.x), 1e-8f);
                float gw  = fmaxf(__fsub_rn(q.w,q.y), 1e-8f);
                float gcy = __fadd_rn(q.x, __fmul_rn(0.5f,gh));
                float gcx = __fadd_rn(q.y, __fmul_rn(0.5f,gw));
                dd.x = xdiv(xdiv(__fsub_rn(gcy,cy), h), 0.1f);
                dd.y = xdiv(xdiv(__fsub_rn(gcx,cx), w), 0.1f);
                dd.z = xdiv(logf(xdiv(gh,h)), 0.2f);
                dd.w = xdiv(logf(xdiv(gw,w)), 0.2f);
            }
        } else {
            int j = t - NUM_POS;
            if (j < nc) {
                int p = s_neg[j];
                roi = props[b*NP + p];
            }
        }

        ((float4*)(out + ROIS_OFF))[b*TRAIN_ROIS + t]  = roi;
        out[CLS_OFF + b*TRAIN_ROIS + t]                = c;
        ((float4*)(out + DELTA_OFF))[b*TRAIN_ROIS + t] = dd;
    }
}

// ---------------------------------------------------------------------------
// Kernel 3: masks for ALL 200 slots per batch (bilinear crop for selected
// positives, zeros elsewhere).
// ---------------------------------------------------------------------------
__global__ void mask_kernel(const float4* __restrict__ props,
                            const unsigned int* __restrict__ masks,
                            float* __restrict__ out)
{
    int b = blockIdx.y, i = blockIdx.x;
    int t = threadIdx.x;                  // 0..783
    float* dst = out + MASK_OFF + ((size_t)b*TRAIN_ROIS + i)*(MASK_H*MASK_W);

    if (i >= g_poscount[b]) { dst[t] = 0.0f; return; }

    int p = g_poslist[b*NUM_POS + i];
    float4 r = props[b*NP + p];
    int g = g_arg[b*NP + p];

    int y = t / MASK_W, x = t % MASK_W;

    float fy = xdiv((float)y, (float)(MASK_H-1));
    float fx = xdiv((float)x, (float)(MASK_W-1));
    float sy = __fadd_rn(__fmul_rn(r.x, 319.f),
                         __fmul_rn(__fmul_rn(fy, __fsub_rn(r.z,r.x)), 319.f));
    sy = fminf(fmaxf(sy, 0.f), 319.f);
    float sx = __fadd_rn(__fmul_rn(r.y, 319.f),
                         __fmul_rn(__fmul_rn(fx, __fsub_rn(r.w,r.y)), 319.f));
    sx = fminf(fmaxf(sx, 0.f), 319.f);

    int y0 = min(max((int)floorf(sy), 0), MH-2);
    int x0 = min(max((int)floorf(sx), 0), MW-2);
    float wy = __fsub_rn(sy, (float)y0);
    float wx = __fsub_rn(sx, (float)x0);

    size_t i00 = (((size_t)b*MH + y0)*MW + x0)*NG + g;
    float c00 = masks[i00]                    ? 1.f : 0.f;
    float c01 = masks[i00 + NG]               ? 1.f : 0.f;
    float c10 = masks[i00 + (size_t)MW*NG]    ? 1.f : 0.f;
    float c11 = masks[i00 + (size_t)MW*NG+NG] ? 1.f : 0.f;

    float top = __fadd_rn(__fmul_rn(c00, __fsub_rn(1.f,wx)), __fmul_rn(c01, wx));
    float bot = __fadd_rn(__fmul_rn(c10, __fsub_rn(1.f,wx)), __fmul_rn(c11, wx));
    float val = __fadd_rn(__fmul_rn(top, __fsub_rn(1.f,wy)), __fmul_rn(bot, wy));

    dst[t] = rintf(val);
}

// ---------------------------------------------------------------------------
extern "C" void kernel_launch(void* const* d_in, const int* in_sizes, int n_in,
                              void* d_out, int out_size)
{
    const float4*       props = 0;
    const int*          cls   = 0;
    const float4*       gts   = 0;
    const unsigned int* masks = 0;
    for (int i = 0; i < n_in; ++i) {
        switch (in_sizes[i]) {
            case BN*NP*4:              props = (const float4*)d_in[i];       break;
            case BN*NG:                cls   = (const int*)d_in[i];          break;
            case BN*NG*4:              gts   = (const float4*)d_in[i];       break;
            default:                   masks = (const unsigned int*)d_in[i]; break;
        }
    }
    float* out = (float*)d_out;

    iou_kernel<<<dim3((NP*4 + 255)/256, BN), 256>>>(props, gts);
    select_kernel<<<BN, 1024>>>(props, gts, cls, out);
    mask_kernel<<<dim3(TRAIN_ROIS, BN), MASK_H*MASK_W>>>(props, masks, out);
}

// round 11
// speedup vs baseline: 1.0971x; 1.0537x over previous
#include <cuda_runtime.h>

#define BN 8
#define NP 2000
#define NG 100
#define MH 320
#define MW 320
#define NUM_POS 66
#define NUM_NEG 134
#define TRAIN_ROIS 200
#define MASK_H 28
#define MASK_W 28

// output layout (flattened tuple, float32)
#define ROIS_OFF  0
#define CLS_OFF   (BN*TRAIN_ROIS*4)            /* 6400 */
#define DELTA_OFF (CLS_OFF + BN*TRAIN_ROIS)    /* 8000 */
#define MASK_OFF  (DELTA_OFF + BN*TRAIN_ROIS*4)/* 14400 */

__device__ unsigned g_keyhi[BN*NP];   // ~orderable(maxiou): ascending = value desc
__device__ int      g_arg[BN*NP];
__device__ unsigned char g_valid[BN*NP];
__device__ int g_poslist[BN*NUM_POS];
__device__ int g_poscount[BN];

// XLA GPU compiles f32 divide with nvptx-prec-divf32=1 -> div.full.f32.
__device__ __forceinline__ float xdiv(float a, float b) {
    float r;
    asm("div.full.f32 %0, %1, %2;" : "=f"(r) : "f"(a), "f"(b));
    return r;
}

__device__ __forceinline__ unsigned orderable(float v) {
    unsigned u = __float_as_uint(v);
    return (u & 0x80000000u) ? ~u : (u | 0x80000000u);
}
// v >= 0.5 <=> hi = ~ord(v) <= ~ord(0.5) = 0x40FFFFFF
__device__ __forceinline__ int pos_hi(unsigned hi) { return hi <= 0x40FFFFFFu; }

// ---------------------------------------------------------------------------
// Kernel 1: IoU max/argmax. One batch per grid.y; GTs staged in shared once
// per 256-thread block. 4 threads per proposal (25 GTs each) + shuffle
// max-reduce of packed (orderable(v)<<32)|(NG-1-g): max = highest value,
// tie -> lowest g = sequential first-max (jnp.argmax).
// ---------------------------------------------------------------------------
__global__ __launch_bounds__(256) void iou_kernel(const float4* __restrict__ props,
                                                  const float4* __restrict__ gts)
{
    __shared__ float4 sg[NG];
    __shared__ unsigned char svg[NG];

    int b = blockIdx.y;
    int tid = threadIdx.x;

    if (tid < NG) {
        float4 q = gts[b*NG + tid];
        sg[tid] = q;
        svg[tid] = (q.x!=0.f)||(q.y!=0.f)||(q.z!=0.f)||(q.w!=0.f);
    }
    __syncthreads();

    int task = blockIdx.x * 256 + tid;   // 4 tasks per proposal
    int pi   = task >> 2;
    int sub  = task & 3;
    if (pi >= NP) return;
    int pid = b*NP + pi;

    float4 p = props[pid];
    unsigned char valid = (p.x!=0.f)||(p.y!=0.f)||(p.z!=0.f)||(p.w!=0.f);
    float area_a = __fmul_rn(__fsub_rn(p.z,p.x), __fsub_rn(p.w,p.y));

    unsigned long long bestk = 0ull;
    int g0 = sub * (NG/4);
    #pragma unroll 5
    for (int gg = 0; gg < NG/4; ++gg) {
        int g = g0 + gg;
        float4 q = sg[g];
        float y1 = fmaxf(p.x, q.x), x1 = fmaxf(p.y, q.y);
        float y2 = fminf(p.z, q.z), x2 = fminf(p.w, q.w);
        float inter = __fmul_rn(fmaxf(__fsub_rn(y2,y1),0.f),
                                fmaxf(__fsub_rn(x2,x1),0.f));
        float area_b = __fmul_rn(__fsub_rn(q.z,q.x), __fsub_rn(q.w,q.y));
        float uni = __fsub_rn(__fadd_rn(area_a, area_b), inter);
        float iou = xdiv(inter, fmaxf(uni, 1e-8f));
        float v = (svg[g] && valid) ? iou : -1.0f;
        unsigned long long k = (((unsigned long long)orderable(v)) << 32)
                             | (unsigned)(NG - 1 - g);
        if (k > bestk) bestk = k;
    }

    #pragma unroll
    for (int off = 1; off < 4; off <<= 1) {
        unsigned long long o = __shfl_xor_sync(0xFFFFFFFFu, bestk, off);
        if (o > bestk) bestk = o;
    }

    if (sub == 0) {
        g_keyhi[pid] = ~((unsigned)(bestk >> 32));
        g_arg[pid]   = NG - 1 - (int)(bestk & 0xFFFFFFFFu);
        g_valid[pid] = valid;
    }
}

// ---------------------------------------------------------------------------
// Register/shuffle bitonic helpers. Same comparator network as the smem
// version: for each (k, j), pair (i, i^j), ascending iff (i & k)==0.
// ---------------------------------------------------------------------------
__device__ __forceinline__ unsigned long long u64sel(bool keep_min,
                                                     unsigned long long a,
                                                     unsigned long long b) {
    unsigned long long mn = a < b ? a : b;
    unsigned long long mx = a < b ? b : a;
    return keep_min ? mn : mx;
}

template<int K>
__device__ __forceinline__ void warp_phases(unsigned long long &r0,
                                            unsigned long long &r1,
                                            int i0, int i1) {
    #pragma unroll
    for (int j = ((K>>1) < 32 ? (K>>1) : 32); j >= 1; j >>= 1) {
        if (j == 32) {
            // in-thread exchange between r0 (i0) and r1 (i1 = i0+32)
            bool up = ((i0 & K) == 0);
            if ((r0 > r1) == up) { unsigned long long tmp = r0; r0 = r1; r1 = tmp; }
        } else {
            unsigned long long o0 = __shfl_xor_sync(0xFFFFFFFFu, r0, j);
            bool up0 = ((i0 & K) == 0), lo0 = ((i0 & j) == 0);
            r0 = u64sel(up0 == lo0, r0, o0);
            unsigned long long o1 = __shfl_xor_sync(0xFFFFFFFFu, r1, j);
            bool up1 = ((i1 & K) == 0), lo1 = ((i1 & j) == 0);
            r1 = u64sel(up1 == lo1, r1, o1);
        }
    }
}

// ---------------------------------------------------------------------------
// Kernel 2 (one block of 1024 per batch): sort + select + slots.
// Elements live in registers (2/thread); only strides j>=64 go through smem.
// ---------------------------------------------------------------------------
__global__ __launch_bounds__(1024) void select_kernel(const float4* __restrict__ props,
                                                      const float4* __restrict__ gts,
                                                      const int*    __restrict__ cls,
                                                      float* __restrict__ out)
{
    int b = blockIdx.x, t = threadIdx.x;
    int lane = t & 31, wid = t >> 5;
    __shared__ unsigned long long keys[2048];
    __shared__ unsigned char svalid[2048];
    __shared__ int warpsum[32];
    __shared__ int s_pos[NUM_POS];
    __shared__ int s_neg[NUM_NEG];
    __shared__ int s_cnt[4];

    // stage validity
    #pragma unroll
    for (int rep = 0; rep < 2; ++rep) {
        int i = t + rep*1024;
        svalid[i] = (i < NP) ? g_valid[b*NP + i] : 0;
    }

    // load this thread's two elements straight into registers
    int i0 = wid*64 + lane, i1 = i0 + 32;
    unsigned long long r0 = (i0 < NP)
        ? ((((unsigned long long)g_keyhi[b*NP + i0]) << 32) | (unsigned)i0) : ~0ull;
    unsigned long long r1 = (i1 < NP)
        ? ((((unsigned long long)g_keyhi[b*NP + i1]) << 32) | (unsigned)i1) : ~0ull;

    // ---- warp-local stages k=2..64 (all strides <= 32) ----
    warp_phases<2>(r0, r1, i0, i1);
    warp_phases<4>(r0, r1, i0, i1);
    warp_phases<8>(r0, r1, i0, i1);
    warp_phases<16>(r0, r1, i0, i1);
    warp_phases<32>(r0, r1, i0, i1);
    warp_phases<64>(r0, r1, i0, i1);

    // ---- stages k=128..2048: j>=64 via smem, then j<=32 in registers ----
    #define BIG_K(K)                                                          \
    {                                                                         \
        keys[i0] = r0; keys[i1] = r1;                                         \
        __syncthreads();                                                      \
        _Pragma("unroll")                                                     \
        for (int j = (K)>>1; j >= 64; j >>= 1) {                              \
            int i  = ((t & ~(j-1)) << 1) | (t & (j-1));                       \
            int ix = i | j;                                                   \
            bool up = ((i & (K)) == 0);                                       \
            unsigned long long a = keys[i], c = keys[ix];                     \
            if ((a > c) == up) { keys[i] = c; keys[ix] = a; }                 \
            __syncthreads();                                                  \
        }                                                                     \
        r0 = keys[i0]; r1 = keys[i1];                                         \
        warp_phases<K>(r0, r1, i0, i1);                                       \
    }
    BIG_K(128)
    BIG_K(256)
    BIG_K(512)
    BIG_K(1024)
    BIG_K(2048)
    #undef BIG_K

    // publish sorted array for extraction
    keys[i0] = r0; keys[i1] = r1;
    __syncthreads();

    // ---- filtered extraction (pass 0: pos, pass 1: neg) ----
    for (int pass = 0; pass < 2; ++pass) {
        unsigned long long k0 = keys[2*t], k1 = keys[2*t+1];
        unsigned hi0 = (unsigned)(k0 >> 32), hi1 = (unsigned)(k1 >> 32);
        unsigned id0 = (unsigned)(k0 & 0xFFFFFFFFu), id1 = (unsigned)(k1 & 0xFFFFFFFFu);
        int fa, fb;
        if (pass == 0) {
            fa = pos_hi(hi0);
            fb = pos_hi(hi1);
        } else {
            fa = (id0 < NP) && !pos_hi(hi0) && svalid[id0];
            fb = (id1 < NP) && !pos_hi(hi1) && svalid[id1];
        }
        int s = fa + fb;
        int x = s;
        #pragma unroll
        for (int off = 1; off < 32; off <<= 1) {
            int y = __shfl_up_sync(0xFFFFFFFFu, x, off);
            if (lane >= off) x += y;
        }
        if (lane == 31) warpsum[wid] = x;
        __syncthreads();
        if (t < 32) {
            int v = warpsum[t];
            #pragma unroll
            for (int off = 1; off < 32; off <<= 1) {
                int y = __shfl_up_sync(0xFFFFFFFFu, v, off);
                if (t >= off) v += y;
            }
            warpsum[t] = v;
        }
        __syncthreads();
        int incl = x + (wid ? warpsum[wid-1] : 0);
        int excl = incl - s;
        if (pass == 0) {
            if (fa && excl < NUM_POS)        s_pos[excl]      = (int)id0;
            if (fb && (excl + fa) < NUM_POS) s_pos[excl + fa] = (int)id1;
        } else {
            if (fa && excl < NUM_NEG)        s_neg[excl]      = (int)id0;
            if (fb && (excl + fa) < NUM_NEG) s_neg[excl + fa] = (int)id1;
        }
        if (t == 0) s_cnt[pass] = warpsum[31];
        __syncthreads();
    }

    if (t == 0) {
        int pc = min(s_cnt[0], NUM_POS);
        int nc = (int)xdiv((float)pc, 0.33f) - pc;   // reference's div.full
        nc = min(nc, s_cnt[1]);
        nc = min(nc, NUM_NEG);
        if (nc < 0) nc = 0;
        s_cnt[2] = pc;
        s_cnt[3] = nc;
        g_poscount[b] = pc;
    }
    __syncthreads();
    int pc = s_cnt[2], nc = s_cnt[3];

    if (t < NUM_POS && t < pc) g_poslist[b*NUM_POS + t] = s_pos[t];

    // ---- slots tail: rois / class / deltas for all 200 slots ----
    if (t < TRAIN_ROIS) {
        float4 roi = make_float4(0.f,0.f,0.f,0.f);
        float  c   = 0.f;
        float4 dd  = make_float4(0.f,0.f,0.f,0.f);

        if (t < NUM_POS) {
            if (t < pc) {
                int p = s_pos[t];
                float4 r = props[b*NP + p];
                roi = r;
                int g = g_arg[b*NP + p];
                c = (float)cls[b*NG + g];
                float4 q = gts[b*NG + g];
                float h  = fmaxf(__fsub_rn(r.z,r.x), 1e-8f);
                float w  = fmaxf(__fsub_rn(r.w,r.y), 1e-8f);
                float cy = __fadd_rn(r.x, __fmul_rn(0.5f,h));
                float cx = __fadd_rn(r.y, __fmul_rn(0.5f,w));
                float gh  = fmaxf(__fsub_rn(q.z,q.x), 1e-8f);
                float gw  = fmaxf(__fsub_rn(q.w,q.y), 1e-8f);
                float gcy = __fadd_rn(q.x, __fmul_rn(0.5f,gh));
                float gcx = __fadd_rn(q.y, __fmul_rn(0.5f,gw));
                dd.x = xdiv(xdiv(__fsub_rn(gcy,cy), h), 0.1f);
                dd.y = xdiv(xdiv(__fsub_rn(gcx,cx), w), 0.1f);
                dd.z = xdiv(logf(xdiv(gh,h)), 0.2f);
                dd.w = xdiv(logf(xdiv(gw,w)), 0.2f);
            }
        } else {
            int j = t - NUM_POS;
            if (j < nc) {
                int p = s_neg[j];
                roi = props[b*NP + p];
            }
        }

        ((float4*)(out + ROIS_OFF))[b*TRAIN_ROIS + t]  = roi;
        out[CLS_OFF + b*TRAIN_ROIS + t]                = c;
        ((float4*)(out + DELTA_OFF))[b*TRAIN_ROIS + t] = dd;
    }
}

// ---------------------------------------------------------------------------
// Kernel 3: masks for ALL 200 slots per batch. Per-row/col quantities
// (sy,y0,wy / sx,x0,wx) computed once by 56 threads with the identical
// instruction sequence, then shared: bit-identical, ~10x less ALU per px.
// ---------------------------------------------------------------------------
__global__ void mask_kernel(const float4* __restrict__ props,
                            const unsigned int* __restrict__ masks,
                            float* __restrict__ out)
{
    int b = blockIdx.y, i = blockIdx.x;
    int t = threadIdx.x;                  // 0..783
    float* dst = out + MASK_OFF + ((size_t)b*TRAIN_ROIS + i)*(MASK_H*MASK_W);

    if (i >= g_poscount[b]) { dst[t] = 0.0f; return; }

    __shared__ int   s_y0[MASK_H], s_x0[MASK_W];
    __shared__ float s_wy[MASK_H], s_wx[MASK_W];

    int p = g_poslist[b*NUM_POS + i];
    float4 r = props[b*NP + p];
    int g = g_arg[b*NP + p];

    if (t < MASK_H) {
        float fy = xdiv((float)t, (float)(MASK_H-1));
        float sy = __fadd_rn(__fmul_rn(r.x, 319.f),
                             __fmul_rn(__fmul_rn(fy, __fsub_rn(r.z,r.x)), 319.f));
        sy = fminf(fmaxf(sy, 0.f), 319.f);
        int y0 = min(max((int)floorf(sy), 0), MH-2);
        s_y0[t] = y0;
        s_wy[t] = __fsub_rn(sy, (float)y0);
    } else if (t < MASK_H + MASK_W) {
        int x = t - MASK_H;
        float fx = xdiv((float)x, (float)(MASK_W-1));
        float sx = __fadd_rn(__fmul_rn(r.y, 319.f),
                             __fmul_rn(__fmul_rn(fx, __fsub_rn(r.w,r.y)), 319.f));
        sx = fminf(fmaxf(sx, 0.f), 319.f);
        int x0 = min(max((int)floorf(sx), 0), MW-2);
        s_x0[x] = x0;
        s_wx[x] = __fsub_rn(sx, (float)x0);
    }
    __syncthreads();

    int y = t / MASK_W, x = t % MASK_W;
    int y0 = s_y0[y], x0 = s_x0[x];
    float wy = s_wy[y], wx = s_wx[x];

    size_t i00 = (((size_t)b*MH + y0)*MW + x0)*NG + g;
    float c00 = masks[i00]                    ? 1.f : 0.f;
    float c01 = masks[i00 + NG]               ? 1.f : 0.f;
    float c10 = masks[i00 + (size_t)MW*NG]    ? 1.f : 0.f;
    float c11 = masks[i00 + (size_t)MW*NG+NG] ? 1.f : 0.f;

    float top = __fadd_rn(__fmul_rn(c00, __fsub_rn(1.f,wx)), __fmul_rn(c01, wx));
    float bot = __fadd_rn(__fmul_rn(c10, __fsub_rn(1.f,wx)), __fmul_rn(c11, wx));
    float val = __fadd_rn(__fmul_rn(top, __fsub_rn(1.f,wy)), __fmul_rn(bot, wy));

    dst[t] = rintf(val);
}

// ---------------------------------------------------------------------------
extern "C" void kernel_launch(void* const* d_in, const int* in_sizes, int n_in,
                              void* d_out, int out_size)
{
    const float4*       props = 0;
    const int*          cls   = 0;
    const float4*       gts   = 0;
    const unsigned int* masks = 0;
    for (int i = 0; i < n_in; ++i) {
        switch (in_sizes[i]) {
            case BN*NP*4:              props = (const float4*)d_in[i];       break;
            case BN*NG:                cls   = (const int*)d_in[i];          break;
            case BN*NG*4:              gts   = (const float4*)d_in[i];       break;
            default:                   masks = (const unsigned int*)d_in[i]; break;
        }
    }
    float* out = (float*)d_out;

    iou_kernel<<<dim3((NP*4 + 255)/256, BN), 256>>>(props, gts);
    select_kernel<<<BN, 1024>>>(props, gts, cls, out);
    mask_kernel<<<dim3(TRAIN_ROIS, BN), MASK_H*MASK_W>>>(props, masks, out);
}